// round 2
// baseline (speedup 1.0000x reference)
#include <cuda_runtime.h>
#include <math.h>

#define NODES   40000
#define EDGES   400000
#define GRAPHS  128
#define IN_F    768
#define HIDD    128
#define HEADS1  4
#define NEG_SLOPE 0.2f

// ---------------- scratch (device globals, no allocation) ----------------
__device__ float g_feat1[(size_t)NODES * HEADS1 * HIDD]; // x@W1           [N,512]
__device__ float g_h1  [(size_t)NODES * HEADS1 * HIDD];  // layer1 out     [N,512]
__device__ float g_feat2[(size_t)NODES * HIDD];          // h1@W2          [N,128]
__device__ float g_h2  [(size_t)NODES * HIDD];           // layer2 out     [N,128]
__device__ float g_tmp [(size_t)NODES * HIDD];           // node-MLP hidden
__device__ float g_el  [(size_t)NODES * HEADS1];
__device__ float g_er  [(size_t)NODES * HEADS1];
__device__ int   g_deg [NODES];
__device__ int   g_rowptr[NODES + 1];
__device__ int   g_next[NODES];
__device__ int   g_csrc[EDGES];      // src node of edges, grouped by dst
__device__ float g_gsum[GRAPHS * HIDD];
__device__ float g_gcnt[GRAPHS];

// ---------------- CSR build ----------------
__global__ void zero_deg_k() {
    int i = blockIdx.x * blockDim.x + threadIdx.x;
    if (i < NODES) g_deg[i] = 0;
}
__global__ void count_k(const int* __restrict__ dst) {
    int e = blockIdx.x * blockDim.x + threadIdx.x;
    if (e < EDGES) atomicAdd(&g_deg[dst[e]], 1);
}
// single-block inclusive scan over g_deg -> g_rowptr, g_next
__global__ void scan_k() {
    __shared__ int sm[1024];
    __shared__ int carry;
    if (threadIdx.x == 0) { carry = 0; g_rowptr[0] = 0; }
    __syncthreads();
    for (int base = 0; base < NODES; base += 1024) {
        int i = base + threadIdx.x;
        int v = (i < NODES) ? g_deg[i] : 0;
        sm[threadIdx.x] = v;
        __syncthreads();
        for (int off = 1; off < 1024; off <<= 1) {
            int mine  = sm[threadIdx.x];
            int other = (threadIdx.x >= off) ? sm[threadIdx.x - off] : 0;
            __syncthreads();
            sm[threadIdx.x] = mine + other;
            __syncthreads();
        }
        int incl = sm[threadIdx.x] + carry;
        if (i < NODES) {
            g_rowptr[i + 1] = incl;
            g_next[i] = incl - v;   // == rowptr[i]
        }
        __syncthreads();
        if (threadIdx.x == 1023) carry += sm[1023];
        __syncthreads();
    }
}
__global__ void fill_k(const int* __restrict__ src, const int* __restrict__ dst) {
    int e = blockIdx.x * blockDim.x + threadIdx.x;
    if (e < EDGES) {
        int d = dst[e];
        int p = atomicAdd(&g_next[d], 1);
        g_csrc[p] = src[e];
    }
}

// ---------------- SGEMM: C = act(A[MxK] @ B[KxN] + bias) ----------------
// 128x128x8 tile, 256 threads, 8x8 micro-tile. N%128==0, K%8==0 assumed.
__global__ void __launch_bounds__(256, 2)
sgemm_k(const float* __restrict__ A, const float* __restrict__ B,
        const float* __restrict__ bias, float* __restrict__ C,
        int M, int N, int K, int relu) {
    __shared__ float As[8][128];
    __shared__ float Bs[8][128];
    const int tid = threadIdx.x;
    const int bm = blockIdx.y * 128, bn = blockIdx.x * 128;
    const int tx = tid & 15, ty = tid >> 4;
    const int arow = tid >> 1, acol = (tid & 1) * 4;
    const int brow = tid >> 5, bcol = (tid & 31) * 4;

    float acc[8][8];
#pragma unroll
    for (int i = 0; i < 8; i++)
#pragma unroll
        for (int j = 0; j < 8; j++) acc[i][j] = 0.f;

    const bool avalid = (bm + arow) < M;
    const float* Aptr = A + (size_t)(bm + arow) * K + acol;
    const float* Bptr = B + (size_t)brow * N + bn + bcol;

    for (int k0 = 0; k0 < K; k0 += 8) {
        float4 a4 = make_float4(0.f, 0.f, 0.f, 0.f);
        if (avalid) a4 = *(const float4*)(Aptr + k0);
        As[acol + 0][arow] = a4.x;
        As[acol + 1][arow] = a4.y;
        As[acol + 2][arow] = a4.z;
        As[acol + 3][arow] = a4.w;
        float4 b4 = *(const float4*)(Bptr + (size_t)k0 * N);
        *(float4*)&Bs[brow][bcol] = b4;
        __syncthreads();
#pragma unroll
        for (int kk = 0; kk < 8; kk++) {
            float4 a0 = *(float4*)&As[kk][ty * 4];
            float4 a1 = *(float4*)&As[kk][64 + ty * 4];
            float4 b0 = *(float4*)&Bs[kk][tx * 4];
            float4 b1 = *(float4*)&Bs[kk][64 + tx * 4];
            float av[8] = {a0.x, a0.y, a0.z, a0.w, a1.x, a1.y, a1.z, a1.w};
            float bv[8] = {b0.x, b0.y, b0.z, b0.w, b1.x, b1.y, b1.z, b1.w};
#pragma unroll
            for (int i = 0; i < 8; i++)
#pragma unroll
                for (int j = 0; j < 8; j++) acc[i][j] += av[i] * bv[j];
        }
        __syncthreads();
    }
    // epilogue
#pragma unroll
    for (int i = 0; i < 8; i++) {
        int gm = bm + ((i < 4) ? (ty * 4 + i) : (64 + ty * 4 + (i - 4)));
        if (gm >= M) continue;
#pragma unroll
        for (int jg = 0; jg < 2; jg++) {
            int col = bn + (jg ? (64 + tx * 4) : (tx * 4));
            float4 v = make_float4(acc[i][jg * 4 + 0], acc[i][jg * 4 + 1],
                                   acc[i][jg * 4 + 2], acc[i][jg * 4 + 3]);
            if (bias) {
                v.x += bias[col + 0]; v.y += bias[col + 1];
                v.z += bias[col + 2]; v.w += bias[col + 3];
            }
            if (relu) {
                v.x = fmaxf(v.x, 0.f); v.y = fmaxf(v.y, 0.f);
                v.z = fmaxf(v.z, 0.f); v.w = fmaxf(v.w, 0.f);
            }
            *(float4*)&C[(size_t)gm * N + col] = v;
        }
    }
}

// ---------------- el/er: per-node per-head dot with attention vectors ---
__global__ void eler_k(const float* __restrict__ feat,
                       const float* __restrict__ al, const float* __restrict__ ar,
                       int heads) {
    int n = blockIdx.x;
    int h = threadIdx.x >> 5;
    int lane = threadIdx.x & 31;
    const float* f = feat + (size_t)n * heads * HIDD + h * HIDD;
    float sl = 0.f, sr = 0.f;
#pragma unroll
    for (int j = lane; j < HIDD; j += 32) {
        float v = f[j];
        sl += v * al[h * HIDD + j];
        sr += v * ar[h * HIDD + j];
    }
#pragma unroll
    for (int off = 16; off > 0; off >>= 1) {
        sl += __shfl_down_sync(0xffffffffu, sl, off);
        sr += __shfl_down_sync(0xffffffffu, sr, off);
    }
    if (lane == 0) {
        g_el[n * heads + h] = sl;
        g_er[n * heads + h] = sr;
    }
}

// ---------------- GAT aggregation: warp per (node, head) ----------------
// pass1: segment max; pass2: sum exp and weighted feature sum; divide.
__global__ void agg_k(const float* __restrict__ feat,
                      const float* __restrict__ bias,
                      float* __restrict__ out, int heads) {
    int n = blockIdx.x;
    int h = threadIdx.x >> 5;
    int lane = threadIdx.x & 31;
    int s0 = g_rowptr[n], s1 = g_rowptr[n + 1];
    float ern = g_er[n * heads + h];
    int stride = heads * HIDD;

    float m = -INFINITY;
    for (int i = s0; i < s1; i++) {
        int s = g_csrc[i];
        float e = g_el[s * heads + h] + ern;
        e = (e > 0.f) ? e : NEG_SLOPE * e;
        m = fmaxf(m, e);
    }
    float denom = 0.f;
    float a0 = 0.f, a1 = 0.f, a2 = 0.f, a3 = 0.f;
    for (int i = s0; i < s1; i++) {
        int s = g_csrc[i];
        float e = g_el[s * heads + h] + ern;
        e = (e > 0.f) ? e : NEG_SLOPE * e;
        float w = __expf(e - m);
        denom += w;
        const float* f = feat + (size_t)s * stride + h * HIDD + lane;
        a0 += w * f[0];
        a1 += w * f[32];
        a2 += w * f[64];
        a3 += w * f[96];
    }
    float inv = (s1 > s0) ? (1.f / denom) : 0.f;
    float* o = out + (size_t)n * stride + h * HIDD + lane;
    const float* b = bias + h * HIDD + lane;
    o[0]  = a0 * inv + b[0];
    o[32] = a1 * inv + b[32];
    o[64] = a2 * inv + b[64];
    o[96] = a3 * inv + b[96];
}

// ---------------- graph pooling ----------------
__global__ void gzero_k() {
    int i = blockIdx.x * blockDim.x + threadIdx.x;
    if (i < GRAPHS * HIDD) g_gsum[i] = 0.f;
    if (i < GRAPHS) g_gcnt[i] = 0.f;
}
__global__ void gpool_k(const int* __restrict__ gid) {
    int n = blockIdx.x;
    int t = threadIdx.x;
    int g = gid[n];
    atomicAdd(&g_gsum[g * HIDD + t], g_h2[(size_t)n * HIDD + t]);
    if (t == 0) atomicAdd(&g_gcnt[g], 1.f);
}

// ---------------- node head: out = tmp @ nW2 + nb2, warp per node -------
__global__ void head_k(const float* __restrict__ in, const float* __restrict__ W,
                       const float* __restrict__ b, float* __restrict__ out,
                       int nrows) {
    int warp = (blockIdx.x * blockDim.x + threadIdx.x) >> 5;
    int lane = threadIdx.x & 31;
    if (warp >= nrows) return;
    float p0 = 0.f, p1 = 0.f;
    const float* r = in + (size_t)warp * HIDD;
#pragma unroll
    for (int j = lane; j < HIDD; j += 32) {
        float v = r[j];
        p0 += v * W[j * 2 + 0];
        p1 += v * W[j * 2 + 1];
    }
#pragma unroll
    for (int off = 16; off > 0; off >>= 1) {
        p0 += __shfl_down_sync(0xffffffffu, p0, off);
        p1 += __shfl_down_sync(0xffffffffu, p1, off);
    }
    if (lane == 0) {
        out[warp * 2 + 0] = p0 + b[0];
        out[warp * 2 + 1] = p1 + b[1];
    }
}

// ---------------- graph MLP (mean -> relu MLP -> 2 logits) --------------
__global__ void gmlp_k(const float* __restrict__ gW1, const float* __restrict__ gb1,
                       const float* __restrict__ gW2, const float* __restrict__ gb2,
                       float* __restrict__ out) {
    int g = blockIdx.x;
    int t = threadIdx.x;
    __shared__ float h[HIDD];
    __shared__ float hid[HIDD];
    __shared__ float red[HIDD];
    float inv = 1.f / fmaxf(g_gcnt[g], 1.f);
    h[t] = g_gsum[g * HIDD + t] * inv;
    __syncthreads();
    float acc = gb1[t];
    for (int k = 0; k < HIDD; k++) acc += h[k] * gW1[k * HIDD + t];
    hid[t] = fmaxf(acc, 0.f);
    __syncthreads();
    for (int c = 0; c < 2; c++) {
        red[t] = hid[t] * gW2[t * 2 + c];
        __syncthreads();
        for (int off = 64; off > 0; off >>= 1) {
            if (t < off) red[t] += red[t + off];
            __syncthreads();
        }
        if (t == 0) out[g * 2 + c] = red[0] + gb2[c];
        __syncthreads();
    }
}

// ---------------- launch ----------------
extern "C" void kernel_launch(void* const* d_in, const int* in_sizes, int n_in,
                              void* d_out, int out_size) {
    const float* x   = (const float*)d_in[0];
    const int*  src  = (const int*)  d_in[1];
    const int*  dst  = (const int*)  d_in[2];
    const int*  gid  = (const int*)  d_in[3];
    const float* W1  = (const float*)d_in[4];
    const float* al1 = (const float*)d_in[5];
    const float* ar1 = (const float*)d_in[6];
    const float* b1  = (const float*)d_in[7];
    const float* W2  = (const float*)d_in[8];
    const float* al2 = (const float*)d_in[9];
    const float* ar2 = (const float*)d_in[10];
    const float* b2  = (const float*)d_in[11];
    const float* nW1 = (const float*)d_in[12];
    const float* nb1 = (const float*)d_in[13];
    const float* nW2 = (const float*)d_in[14];
    const float* nb2 = (const float*)d_in[15];
    const float* gW1 = (const float*)d_in[16];
    const float* gb1 = (const float*)d_in[17];
    const float* gW2 = (const float*)d_in[18];
    const float* gb2 = (const float*)d_in[19];
    float* out = (float*)d_out;

    float *p_feat1, *p_h1, *p_feat2, *p_h2, *p_tmp;
    cudaGetSymbolAddress((void**)&p_feat1, g_feat1);
    cudaGetSymbolAddress((void**)&p_h1,    g_h1);
    cudaGetSymbolAddress((void**)&p_feat2, g_feat2);
    cudaGetSymbolAddress((void**)&p_h2,    g_h2);
    cudaGetSymbolAddress((void**)&p_tmp,   g_tmp);

    // CSR build (shared by both GAT layers)
    zero_deg_k<<<(NODES + 255) / 256, 256>>>();
    count_k<<<(EDGES + 255) / 256, 256>>>(dst);
    scan_k<<<1, 1024>>>();
    fill_k<<<(EDGES + 255) / 256, 256>>>(src, dst);

    // ---- GAT layer 1 ----
    {
        dim3 grid(HEADS1 * HIDD / 128, (NODES + 127) / 128);
        sgemm_k<<<grid, 256>>>(x, W1, nullptr, p_feat1, NODES, HEADS1 * HIDD, IN_F, 0);
    }
    eler_k<<<NODES, HEADS1 * 32>>>(p_feat1, al1, ar1, HEADS1);
    agg_k<<<NODES, HEADS1 * 32>>>(p_feat1, b1, p_h1, HEADS1);

    // ---- GAT layer 2 ----
    {
        dim3 grid(HIDD / 128, (NODES + 127) / 128);
        sgemm_k<<<grid, 256>>>(p_h1, W2, nullptr, p_feat2, NODES, HIDD, HEADS1 * HIDD, 0);
    }
    eler_k<<<NODES, 32>>>(p_feat2, al2, ar2, 1);
    agg_k<<<NODES, 32>>>(p_feat2, b2, p_h2, 1);

    // ---- graph pooling ----
    gzero_k<<<(GRAPHS * HIDD + 127) / 128, 128>>>();
    gpool_k<<<NODES, HIDD>>>(gid);

    // ---- node MLP ----
    {
        dim3 grid(HIDD / 128, (NODES + 127) / 128);
        sgemm_k<<<grid, 256>>>(p_h2, nW1, nb1, p_tmp, NODES, HIDD, HIDD, 1);
    }
    head_k<<<(NODES * 32 + 255) / 256, 256>>>(p_tmp, nW2, nb2, out, NODES);

    // ---- graph MLP ----
    gmlp_k<<<GRAPHS, HIDD>>>(gW1, gb1, gW2, gb2, out + (size_t)NODES * 2);
}